// round 13
// baseline (speedup 1.0000x reference)
#include <cuda_runtime.h>
#include <cuda_bf16.h>
#include <mma.h>
#include <math.h>
#include <stdint.h>

using namespace nvcuda;

#define TOKENS 8192
#define DIM    1024
#define NQKV   3072
#define HEADS  16
#define DH     64
#define SEG    512
#define NPM    16

// ---------------- scratch (allocation-free: __device__ globals) ----------------
__device__ __align__(16) float g_xn [(size_t)TOKENS * DIM];
__device__ __align__(16) float g_qkv[(size_t)TOKENS * NQKV];
__device__ __align__(16) float g_q  [(size_t)TOKENS * DIM];
__device__ __align__(16) float g_k  [(size_t)TOKENS * DIM];
__device__ __align__(16) float g_ao [(size_t)TOKENS * DIM];
__device__ __align__(16) __nv_bfloat16 g_a_hi[(size_t)TOKENS * DIM];
__device__ __align__(16) __nv_bfloat16 g_a_lo[(size_t)TOKENS * DIM];
__device__ __align__(16) __nv_bfloat16 g_wq_hi[(size_t)NQKV * DIM];
__device__ __align__(16) __nv_bfloat16 g_wq_lo[(size_t)NQKV * DIM];
__device__ __align__(16) __nv_bfloat16 g_wo_hi[(size_t)DIM * DIM];
__device__ __align__(16) __nv_bfloat16 g_wo_lo[(size_t)DIM * DIM];
__device__ __align__(16) __nv_bfloat16 g_o_hi[(size_t)TOKENS * DIM];
__device__ __align__(16) __nv_bfloat16 g_o_lo[(size_t)TOKENS * DIM];
__device__ float g_cos[SEG * 32];
__device__ float g_sin[SEG * 32];
__device__ int   g_bad;

// ---------------- rope table (+ g_bad reset) ----------------------------------
__global__ void rope_table_kernel() {
    int idx = blockIdx.x * blockDim.x + threadIdx.x;
    if (idx == 0) g_bad = 0;
    if (idx >= SEG * 32) return;
    int s = idx >> 5, i = idx & 31;
    double invf = pow(10000.0, -(double)(2 * i) / 64.0);
    double ang = (double)s * invf;
    g_cos[idx] = (float)cos(ang);
    g_sin[idx] = (float)sin(ang);
}

// ---------------- weight transpose + bf16 hi/lo split -------------------------
// W[K=1024][N] fp32 -> Whi/Wlo [N][1024] bf16
__global__ __launch_bounds__(256) void wconv_kernel(const float* __restrict__ W,
                                                    __nv_bfloat16* __restrict__ Whi,
                                                    __nv_bfloat16* __restrict__ Wlo, int N) {
    int idx = blockIdx.x * 256 + threadIdx.x;
    if (idx >= N * DIM) return;
    int n = idx / DIM, k = idx % DIM;
    float v = W[(size_t)k * N + n];
    __nv_bfloat16 h = __float2bfloat16(v);
    Whi[idx] = h;
    Wlo[idx] = __float2bfloat16(v - __bfloat162float(h));
}

// ---------------- RMSNorm -> fp32 + bf16 hi/lo --------------------------------
__global__ __launch_bounds__(256) void rmsnorm_kernel(const float* __restrict__ seq,
                                                      const float* __restrict__ w) {
    int t = blockIdx.x;
    const float* x = seq + (size_t)t * DIM;
    float ss = 0.f;
    for (int i = threadIdx.x; i < DIM; i += 256) { float v = x[i]; ss += v * v; }
    __shared__ float red[8];
    #pragma unroll
    for (int o = 16; o > 0; o >>= 1) ss += __shfl_xor_sync(0xffffffffu, ss, o);
    if ((threadIdx.x & 31) == 0) red[threadIdx.x >> 5] = ss;
    __syncthreads();
    if (threadIdx.x < 8) {
        float v = red[threadIdx.x];
        #pragma unroll
        for (int o = 4; o > 0; o >>= 1) v += __shfl_xor_sync(0xffu, v, o);
        if (threadIdx.x == 0) red[0] = v;
    }
    __syncthreads();
    float r = rsqrtf(red[0] * (1.0f / DIM) + 1.1920929e-07f);
    for (int i = threadIdx.x; i < DIM; i += 256) {
        float v = x[i] * r * w[i];
        g_xn[(size_t)t * DIM + i] = v;
        __nv_bfloat16 h = __float2bfloat16(v);
        g_a_hi[(size_t)t * DIM + i] = h;
        g_a_lo[(size_t)t * DIM + i] = __float2bfloat16(v - __bfloat162float(h));
    }
}

// ---------------- wmma bf16 GEMM (3-term split) -------------------------------
// C[M][Nc] = A[M][1024] @ B^T, A [M][K] hi/lo, B [Nc][K] hi/lo bf16.
// CTA 128x128, BK=16, 8 warps (4x2) of 32x64 warp tiles; wmma m16n16k16.
#define ROWE  32                         // smem row stride in elements (64 B)
#define WTILE (128 * ROWE)               // elements per operand tile

template <int MODE>
__global__ __launch_bounds__(256, 2) void wgemm_kernel(float* __restrict__ Cout, int Nc) {
    __shared__ __align__(16) __nv_bfloat16 sm[4 * WTILE];   // 32 KB static
    const __nv_bfloat16 *Ahi, *Alo, *Bhi, *Blo;
    float* C;
    if (MODE == 0) { Ahi = g_a_hi; Alo = g_a_lo; Bhi = g_wq_hi; Blo = g_wq_lo; C = g_qkv; }
    else           { Ahi = g_o_hi; Alo = g_o_lo; Bhi = g_wo_hi; Blo = g_wo_lo; C = Cout; }

    int tid = threadIdx.x;
    int wid = tid >> 5;
    int warpM = wid >> 1, warpN = wid & 1;
    int rowBase = blockIdx.y * 128;
    int colBase = blockIdx.x * 128;

    const __nv_bfloat16* aH = Ahi + (size_t)rowBase * DIM;
    const __nv_bfloat16* aL = Alo + (size_t)rowBase * DIM;
    const __nv_bfloat16* bH = Bhi + (size_t)colBase * DIM;
    const __nv_bfloat16* bL = Blo + (size_t)colBase * DIM;

    int lrow = tid >> 1, lc = tid & 1;               // 128 rows x 2 uint4 chunks
    size_t goff0 = (size_t)lrow * DIM + lc * 8;
    int    soff  = lrow * ROWE + lc * 8;

    wmma::fragment<wmma::accumulator, 16, 16, 16, float> acc[2][4];
    #pragma unroll
    for (int mi = 0; mi < 2; mi++)
        #pragma unroll
        for (int ni = 0; ni < 4; ni++) wmma::fill_fragment(acc[mi][ni], 0.f);

    uint4 pAH = *(const uint4*)(aH + goff0);
    uint4 pAL = *(const uint4*)(aL + goff0);
    uint4 pBH = *(const uint4*)(bH + goff0);
    uint4 pBL = *(const uint4*)(bL + goff0);

    const int KT = DIM / 16;                          // 64 stages
    for (int kt = 0; kt < KT; kt++) {
        __syncthreads();
        *(uint4*)(&sm[0 * WTILE + soff]) = pAH;
        *(uint4*)(&sm[1 * WTILE + soff]) = pAL;
        *(uint4*)(&sm[2 * WTILE + soff]) = pBH;
        *(uint4*)(&sm[3 * WTILE + soff]) = pBL;
        __syncthreads();
        if (kt + 1 < KT) {
            size_t go = goff0 + (size_t)(kt + 1) * 16;
            pAH = *(const uint4*)(aH + go);
            pAL = *(const uint4*)(aL + go);
            pBH = *(const uint4*)(bH + go);
            pBL = *(const uint4*)(bL + go);
        }

        wmma::fragment<wmma::matrix_a, 16, 16, 16, __nv_bfloat16, wmma::row_major> fah[2], fal[2];
        #pragma unroll
        for (int mi = 0; mi < 2; mi++) {
            int r0 = warpM * 32 + mi * 16;
            wmma::load_matrix_sync(fah[mi], &sm[0 * WTILE + r0 * ROWE], ROWE);
            wmma::load_matrix_sync(fal[mi], &sm[1 * WTILE + r0 * ROWE], ROWE);
        }
        #pragma unroll
        for (int ni = 0; ni < 4; ni++) {
            wmma::fragment<wmma::matrix_b, 16, 16, 16, __nv_bfloat16, wmma::col_major> fbh, fbl;
            int n0 = warpN * 64 + ni * 16;
            wmma::load_matrix_sync(fbh, &sm[2 * WTILE + n0 * ROWE], ROWE);
            wmma::load_matrix_sync(fbl, &sm[3 * WTILE + n0 * ROWE], ROWE);
            #pragma unroll
            for (int mi = 0; mi < 2; mi++) {
                wmma::mma_sync(acc[mi][ni], fah[mi], fbh, acc[mi][ni]);
                wmma::mma_sync(acc[mi][ni], fah[mi], fbl, acc[mi][ni]);
                wmma::mma_sync(acc[mi][ni], fal[mi], fbh, acc[mi][ni]);
            }
        }
    }

    #pragma unroll
    for (int mi = 0; mi < 2; mi++)
        #pragma unroll
        for (int ni = 0; ni < 4; ni++) {
            size_t r = rowBase + warpM * 32 + mi * 16;
            int    c = colBase + warpN * 64 + ni * 16;
            wmma::store_matrix_sync(C + r * Nc + c, acc[mi][ni], Nc, wmma::mem_row_major);
        }
}

// ---------------- device-side verification of wgemm<0> ------------------------
__global__ void gemm_check_kernel(const float* __restrict__ W) {
    int i = threadIdx.x;                              // 128 samples
    int row = (i * 67 + 13) & (TOKENS - 1);
    int col = (i * 29 + 3) % NQKV;
    const float* x = g_xn + (size_t)row * DIM;
    float ref = 0.f;
    for (int k = 0; k < DIM; k++) ref = fmaf(x[k], W[(size_t)k * NQKV + col], ref);
    float got = g_qkv[(size_t)row * NQKV + col];
    if (fabsf(got - ref) > 0.02f + 0.01f * fabsf(ref)) g_bad = 1;
}

// ---------------- SIMT fp32 GEMM fallback (runs only if g_bad) ----------------
template <int MODE>
__global__ __launch_bounds__(256) void sgemm_fb_kernel(const float* __restrict__ B,
                                                       float* __restrict__ Cout, int N) {
    if (g_bad == 0) return;
    constexpr int BM = 128, BN = 128, BK = 16, TM = 8, TN = 8;
    const float* A = (MODE == 0) ? g_xn : g_ao;
    float* C = (MODE == 0) ? g_qkv : Cout;

    __shared__ __align__(16) float As[BK][BM];
    __shared__ __align__(16) float Bs[BK][BN];

    int tid = threadIdx.x;
    int rowBase = blockIdx.y * BM;
    int colBase = blockIdx.x * BN;
    int lrow = tid >> 1, lk = (tid & 1) * 8;
    int brow = tid >> 4, bc = (tid & 15) * 8;
    int tr = (tid / 16) * TM;
    int tc = (tid % 16) * TN;

    const float* Ap = A + (size_t)rowBase * DIM + (size_t)lrow * DIM + lk;
    const float* Bp = B + colBase + (size_t)brow * N + bc;

    float acc[TM * TN];
    #pragma unroll
    for (int i = 0; i < TM * TN; i++) acc[i] = 0.f;

    float4 pa0 = *(const float4*)(Ap + 0);
    float4 pa1 = *(const float4*)(Ap + 4);
    float4 pb0 = *(const float4*)(Bp + 0);
    float4 pb1 = *(const float4*)(Bp + 4);

    const int KT = DIM / BK;
    for (int kt = 0; kt < KT; kt++) {
        As[lk + 0][lrow] = pa0.x; As[lk + 1][lrow] = pa0.y;
        As[lk + 2][lrow] = pa0.z; As[lk + 3][lrow] = pa0.w;
        As[lk + 4][lrow] = pa1.x; As[lk + 5][lrow] = pa1.y;
        As[lk + 6][lrow] = pa1.z; As[lk + 7][lrow] = pa1.w;
        *(float4*)(&Bs[brow][bc])     = pb0;
        *(float4*)(&Bs[brow][bc + 4]) = pb1;
        __syncthreads();
        if (kt + 1 < KT) {
            const float* an = Ap + (kt + 1) * BK;
            const float* bn = Bp + (size_t)(kt + 1) * BK * N;
            pa0 = *(const float4*)(an + 0);
            pa1 = *(const float4*)(an + 4);
            pb0 = *(const float4*)(bn + 0);
            pb1 = *(const float4*)(bn + 4);
        }
        #pragma unroll
        for (int k = 0; k < BK; k++) {
            float rm[TM], rn[TN];
            #pragma unroll
            for (int m = 0; m < TM; m += 4) *(float4*)(rm + m) = *(const float4*)(&As[k][tr + m]);
            #pragma unroll
            for (int n = 0; n < TN; n += 4) *(float4*)(rn + n) = *(const float4*)(&Bs[k][tc + n]);
            #pragma unroll
            for (int m = 0; m < TM; m++)
                #pragma unroll
                for (int n = 0; n < TN; n++)
                    acc[m * TN + n] = fmaf(rm[m], rn[n], acc[m * TN + n]);
        }
        __syncthreads();
    }
    #pragma unroll
    for (int m = 0; m < TM; m++) {
        size_t r = rowBase + tr + m;
        #pragma unroll
        for (int n = 0; n < TN; n += 4)
            *(float4*)(C + r * N + colBase + tc + n) =
                make_float4(acc[m * TN + n], acc[m * TN + n + 1],
                            acc[m * TN + n + 2], acc[m * TN + n + 3]);
    }
}

// ---------------- scatter qkv to (bw,h,s,d) + RoPE; v -> d_out ----------------
__global__ __launch_bounds__(256) void scatter_rope_kernel(float* __restrict__ out_v) {
    int p = blockIdx.x * blockDim.x + threadIdx.x;
    if (p >= TOKENS * (NQKV / 2)) return;
    int t = p / (NQKV / 2);
    int n = (p % (NQKV / 2)) * 2;
    float x0 = g_qkv[(size_t)t * NQKV + n];
    float x1 = g_qkv[(size_t)t * NQKV + n + 1];
    int bw = t / SEG, s = t % SEG;
    int which = n >> 10;
    int nn = n & 1023;
    int h = nn >> 6, d = nn & 63;
    size_t dst = ((size_t)(bw * HEADS + h) * SEG + s) * DH + d;
    if (which == 2) { out_v[dst] = x0; out_v[dst + 1] = x1; return; }
    float c  = g_cos[s * 32 + (d >> 1)];
    float sn = g_sin[s * 32 + (d >> 1)];
    float y0 = x0 * c - x1 * sn;
    float y1 = x1 * c + x0 * sn;
    float* dstp = which ? g_k : g_q;
    dstp[dst] = y0; dstp[dst + 1] = y1;
}

// ---------------- flash attention (SIMT fp32) -> fp32 + bf16 hi/lo ------------
__global__ __launch_bounds__(128) void attn_kernel(const float* __restrict__ vsrc,
                                                   const float* __restrict__ pmem) {
    int bwh = blockIdx.x;
    int h = bwh % HEADS;
    int qt = blockIdx.y;
    int tid = threadIdx.x;

    __shared__ __align__(16) float sm[128 * 64];

    const float* Qb = g_q + ((size_t)bwh * SEG + qt * 128) * DH;
    for (int e = tid; e < 128 * 64; e += 128) sm[e] = Qb[e];
    __syncthreads();
    float q[DH];
    #pragma unroll
    for (int d4 = 0; d4 < DH / 4; d4++) {
        float4 v = *(const float4*)(sm + tid * DH + d4 * 4);
        q[d4 * 4 + 0] = v.x * 0.125f; q[d4 * 4 + 1] = v.y * 0.125f;
        q[d4 * 4 + 2] = v.z * 0.125f; q[d4 * 4 + 3] = v.w * 0.125f;
    }
    __syncthreads();

    float acc[DH];
    #pragma unroll
    for (int d = 0; d < DH; d++) acc[d] = 0.f;
    float m = -1e30f, l = 0.f;
    int i = qt * 128 + tid;
    int nkeys = NPM + i + 1;
    int nch = (NPM + (qt + 1) * 128 + 63) / 64;

    const float* Kb = g_k + (size_t)bwh * SEG * DH;
    const float* Vb = vsrc + (size_t)bwh * SEG * DH;
    const float* PK = pmem + (size_t)h * NPM * DH;
    const float* PV = pmem + (size_t)HEADS * NPM * DH + (size_t)h * NPM * DH;
    float* Ks = sm;
    float* Vs = sm + 64 * 64;

    for (int c = 0; c < nch; c++) {
        for (int e = tid; e < 64 * 64; e += 128) {
            int j = c * 64 + (e >> 6); int d = e & 63;
            float kv, vv;
            if (j < NPM)            { kv = PK[j * DH + d];                 vv = PV[j * DH + d]; }
            else if (j < NPM + SEG) { kv = Kb[(size_t)(j - NPM) * DH + d]; vv = Vb[(size_t)(j - NPM) * DH + d]; }
            else                    { kv = 0.f; vv = 0.f; }
            Ks[e] = kv; Vs[e] = vv;
        }
        __syncthreads();
        int jvalid = nkeys - c * 64;
        #pragma unroll 2
        for (int j = 0; j < 64; j++) {
            float s = 0.f;
            const float4* kp = (const float4*)(Ks + j * 64);
            #pragma unroll
            for (int d4 = 0; d4 < DH / 4; d4++) {
                float4 kk = kp[d4];
                s = fmaf(q[d4 * 4 + 0], kk.x, s);
                s = fmaf(q[d4 * 4 + 1], kk.y, s);
                s = fmaf(q[d4 * 4 + 2], kk.z, s);
                s = fmaf(q[d4 * 4 + 3], kk.w, s);
            }
            if (j >= jvalid) s = -1e30f;
            if (s > m) {
                float corr = __expf(m - s);
                l *= corr;
                #pragma unroll
                for (int d = 0; d < DH; d++) acc[d] *= corr;
                m = s;
            }
            float p = __expf(s - m);
            l += p;
            const float4* vp = (const float4*)(Vs + j * 64);
            #pragma unroll
            for (int d4 = 0; d4 < DH / 4; d4++) {
                float4 vv = vp[d4];
                acc[d4 * 4 + 0] = fmaf(p, vv.x, acc[d4 * 4 + 0]);
                acc[d4 * 4 + 1] = fmaf(p, vv.y, acc[d4 * 4 + 1]);
                acc[d4 * 4 + 2] = fmaf(p, vv.z, acc[d4 * 4 + 2]);
                acc[d4 * 4 + 3] = fmaf(p, vv.w, acc[d4 * 4 + 3]);
            }
        }
        __syncthreads();
    }
    int bw = bwh / HEADS;
    float rl = 1.0f / l;
    size_t obase = ((size_t)(bw * SEG + i)) * DIM + (size_t)h * DH;
    #pragma unroll
    for (int d = 0; d < DH; d += 2) {
        float v0 = acc[d] * rl, v1 = acc[d + 1] * rl;
        g_ao[obase + d] = v0; g_ao[obase + d + 1] = v1;
        __nv_bfloat16 h0 = __float2bfloat16(v0), h1 = __float2bfloat16(v1);
        __nv_bfloat16 l0 = __float2bfloat16(v0 - __bfloat162float(h0));
        __nv_bfloat16 l1 = __float2bfloat16(v1 - __bfloat162float(h1));
        *(__nv_bfloat162*)(g_o_hi + obase + d) = __halves2bfloat162(h0, h1);
        *(__nv_bfloat162*)(g_o_lo + obase + d) = __halves2bfloat162(l0, l1);
    }
}

// ---------------- launch (kernel launches ONLY) --------------------------------
extern "C" void kernel_launch(void* const* d_in, const int* in_sizes, int n_in,
                              void* d_out, int out_size) {
    const float* seq    = (const float*)d_in[0];
    const float* norm_w = (const float*)d_in[1];
    const float* w_qkv  = (const float*)d_in[2];
    const float* w_out  = (const float*)d_in[3];
    const float* pmem   = (const float*)d_in[4];
    float* out   = (float*)d_out;
    float* out_v = out + (size_t)TOKENS * DIM;

    rope_table_kernel<<<64, 256>>>();
    wconv_kernel<<<(NQKV * DIM + 255) / 256, 256>>>(w_qkv, g_wq_hi, g_wq_lo, NQKV);
    wconv_kernel<<<(DIM * DIM + 255) / 256, 256>>>(w_out, g_wo_hi, g_wo_lo, DIM);
    rmsnorm_kernel<<<TOKENS, 256>>>(seq, norm_w);
    wgemm_kernel<0><<<dim3(NQKV / 128, TOKENS / 128), 256>>>(nullptr, NQKV);
    gemm_check_kernel<<<1, 128>>>(w_qkv);
    sgemm_fb_kernel<0><<<dim3(NQKV / 128, TOKENS / 128), 256>>>(w_qkv, nullptr, NQKV);
    scatter_rope_kernel<<<(TOKENS * (NQKV / 2) + 255) / 256, 256>>>(out_v);
    attn_kernel<<<dim3(256, 4), 128>>>(out_v, pmem);
    wgemm_kernel<1><<<dim3(DIM / 128, TOKENS / 128), 256>>>(out, DIM);
    sgemm_fb_kernel<1><<<dim3(DIM / 128, TOKENS / 128), 256>>>(w_out, out, DIM);
}

// round 17
// speedup vs baseline: 2.4386x; 2.4386x over previous
#include <cuda_runtime.h>
#include <cuda_bf16.h>
#include <math.h>
#include <stdint.h>

#define TOKENS 8192
#define DIM    1024
#define NQKV   3072
#define HEADS  16
#define DH     64
#define SEG    512
#define NPM    16

// ------- scratch (allocation-free; NEVER passed as kernel args from host) ------
__device__ __align__(16) float g_xn [(size_t)TOKENS * DIM];
__device__ __align__(16) float g_qkv[(size_t)TOKENS * NQKV];
__device__ __align__(16) float g_q  [(size_t)TOKENS * DIM];
__device__ __align__(16) float g_k  [(size_t)TOKENS * DIM];
__device__ __align__(16) float g_ao [(size_t)TOKENS * DIM];
__device__ __align__(16) __nv_bfloat16 g_a_hi[(size_t)TOKENS * DIM];
__device__ __align__(16) __nv_bfloat16 g_a_lo[(size_t)TOKENS * DIM];
__device__ __align__(16) __nv_bfloat16 g_wq_hi[(size_t)NQKV * DIM];
__device__ __align__(16) __nv_bfloat16 g_wq_lo[(size_t)NQKV * DIM];
__device__ __align__(16) __nv_bfloat16 g_wo_hi[(size_t)DIM * DIM];
__device__ __align__(16) __nv_bfloat16 g_wo_lo[(size_t)DIM * DIM];
__device__ __align__(16) __nv_bfloat16 g_o_hi[(size_t)TOKENS * DIM];
__device__ __align__(16) __nv_bfloat16 g_o_lo[(size_t)TOKENS * DIM];
__device__ float g_cos[SEG * 32];
__device__ float g_sin[SEG * 32];
__device__ int   g_bad;

// ---------------- ptx helpers -------------------------------------------------
__device__ __forceinline__ uint32_t smem_u32(const void* p) {
    uint32_t a;
    asm("{ .reg .u64 t; cvta.to.shared.u64 t, %1; cvt.u32.u64 %0, t; }" : "=r"(a) : "l"(p));
    return a;
}
__device__ __forceinline__ void ldsm4(uint32_t* r, uint32_t addr) {
    asm volatile("ldmatrix.sync.aligned.m8n8.x4.shared.b16 {%0,%1,%2,%3}, [%4];"
                 : "=r"(r[0]), "=r"(r[1]), "=r"(r[2]), "=r"(r[3]) : "r"(addr));
}
__device__ __forceinline__ void mma_bf16(float* c, const uint32_t* a, const uint32_t* b) {
    asm volatile("mma.sync.aligned.m16n8k16.row.col.f32.bf16.bf16.f32 "
                 "{%0,%1,%2,%3}, {%4,%5,%6,%7}, {%8,%9}, {%0,%1,%2,%3};"
                 : "+f"(c[0]), "+f"(c[1]), "+f"(c[2]), "+f"(c[3])
                 : "r"(a[0]), "r"(a[1]), "r"(a[2]), "r"(a[3]), "r"(b[0]), "r"(b[1]));
}

// ---------------- rope table (+ g_bad reset) ----------------------------------
__global__ void rope_table_kernel() {
    int idx = blockIdx.x * blockDim.x + threadIdx.x;
    if (idx == 0) g_bad = 0;
    if (idx >= SEG * 32) return;
    int s = idx >> 5, i = idx & 31;
    double invf = pow(10000.0, -(double)(2 * i) / 64.0);
    double ang = (double)s * invf;
    g_cos[idx] = (float)cos(ang);
    g_sin[idx] = (float)sin(ang);
}

// -------- weight transpose + bf16 hi/lo split (dst selected INSIDE) -----------
// MODE 0: w_qkv[k][3072] -> g_wq_*[n][1024].  MODE 1: w_out[k][1024] -> g_wo_*.
template <int MODE>
__global__ __launch_bounds__(256) void wconv_kernel(const float* __restrict__ W) {
    const int N = (MODE == 0) ? NQKV : DIM;
    __nv_bfloat16* Whi = (MODE == 0) ? g_wq_hi : g_wo_hi;
    __nv_bfloat16* Wlo = (MODE == 0) ? g_wq_lo : g_wo_lo;
    int idx = blockIdx.x * 256 + threadIdx.x;
    if (idx >= N * DIM) return;
    int n = idx / DIM, k = idx % DIM;
    float v = W[(size_t)k * N + n];
    __nv_bfloat16 h = __float2bfloat16(v);
    Whi[idx] = h;
    Wlo[idx] = __float2bfloat16(v - __bfloat162float(h));
}

// ---------------- RMSNorm -> fp32 + bf16 hi/lo --------------------------------
__global__ __launch_bounds__(256) void rmsnorm_kernel(const float* __restrict__ seq,
                                                      const float* __restrict__ w) {
    int t = blockIdx.x;
    const float* x = seq + (size_t)t * DIM;
    float ss = 0.f;
    for (int i = threadIdx.x; i < DIM; i += 256) { float v = x[i]; ss += v * v; }
    __shared__ float red[8];
    #pragma unroll
    for (int o = 16; o > 0; o >>= 1) ss += __shfl_xor_sync(0xffffffffu, ss, o);
    if ((threadIdx.x & 31) == 0) red[threadIdx.x >> 5] = ss;
    __syncthreads();
    if (threadIdx.x < 8) {
        float v = red[threadIdx.x];
        #pragma unroll
        for (int o = 4; o > 0; o >>= 1) v += __shfl_xor_sync(0xffu, v, o);
        if (threadIdx.x == 0) red[0] = v;
    }
    __syncthreads();
    float r = rsqrtf(red[0] * (1.0f / DIM) + 1.1920929e-07f);
    for (int i = threadIdx.x; i < DIM; i += 256) {
        float v = x[i] * r * w[i];
        g_xn[(size_t)t * DIM + i] = v;
        __nv_bfloat16 h = __float2bfloat16(v);
        g_a_hi[(size_t)t * DIM + i] = h;
        g_a_lo[(size_t)t * DIM + i] = __float2bfloat16(v - __bfloat162float(h));
    }
}

// ---------------- HMMA bf16 GEMM (3-term split), r9 datapath -------------------
#define GBK     16
#define ROWB    48
#define GTILE   (128 * ROWB)

template <int MODE>
__global__ __launch_bounds__(256, 2) void gemm_kernel(float* __restrict__ Cout) {
    __shared__ __align__(16) char smem_raw[4 * GTILE];   // 24576 B static
    const int Nc = (MODE == 0) ? NQKV : DIM;
    const __nv_bfloat16* Ahi = (MODE == 0) ? g_a_hi : g_o_hi;
    const __nv_bfloat16* Alo = (MODE == 0) ? g_a_lo : g_o_lo;
    const __nv_bfloat16* Bhi = (MODE == 0) ? g_wq_hi : g_wo_hi;
    const __nv_bfloat16* Blo = (MODE == 0) ? g_wq_lo : g_wo_lo;
    float* C = (MODE == 0) ? g_qkv : Cout;

    int tid = threadIdx.x;
    int wid = tid >> 5, lane = tid & 31;
    int warpM = wid >> 1, warpN = wid & 1;
    int rowBase = blockIdx.y * 128;
    int colBase = blockIdx.x * 128;

    uint32_t sbase = smem_u32(smem_raw);

    const __nv_bfloat16* aH = Ahi + (size_t)rowBase * DIM;
    const __nv_bfloat16* aL = Alo + (size_t)rowBase * DIM;
    const __nv_bfloat16* bH = Bhi + (size_t)colBase * DIM;
    const __nv_bfloat16* bL = Blo + (size_t)colBase * DIM;

    int lrow = tid >> 1, lc = tid & 1;
    size_t goff0 = (size_t)lrow * DIM + lc * 8;
    uint32_t soff = (uint32_t)(lrow * ROWB + lc * 16);

    uint32_t aoff = (uint32_t)((warpM * 32 + (lane & 15)) * ROWB + (lane >> 4) * 16);
    uint32_t boff = (uint32_t)((warpN * 64 + (lane & 7) + ((lane & 16) ? 8 : 0)) * ROWB
                               + ((lane >> 3) & 1) * 16);

    float acc[2][8][4];
    #pragma unroll
    for (int mi = 0; mi < 2; mi++)
        #pragma unroll
        for (int ni = 0; ni < 8; ni++)
            #pragma unroll
            for (int r = 0; r < 4; r++) acc[mi][ni][r] = 0.f;

    uint4 pAH = *(const uint4*)(aH + goff0);
    uint4 pAL = *(const uint4*)(aL + goff0);
    uint4 pBH = *(const uint4*)(bH + goff0);
    uint4 pBL = *(const uint4*)(bL + goff0);

    const int KT = DIM / GBK;
    for (int kt = 0; kt < KT; kt++) {
        __syncthreads();
        *(uint4*)(smem_raw + 0 * GTILE + soff) = pAH;
        *(uint4*)(smem_raw + 1 * GTILE + soff) = pAL;
        *(uint4*)(smem_raw + 2 * GTILE + soff) = pBH;
        *(uint4*)(smem_raw + 3 * GTILE + soff) = pBL;
        __syncthreads();
        if (kt + 1 < KT) {
            size_t go = goff0 + (size_t)(kt + 1) * GBK;
            pAH = *(const uint4*)(aH + go);
            pAL = *(const uint4*)(aL + go);
            pBH = *(const uint4*)(bH + go);
            pBL = *(const uint4*)(bL + go);
        }

        uint32_t ah[2][4], al[2][4];
        #pragma unroll
        for (int mi = 0; mi < 2; mi++) {
            ldsm4(ah[mi], sbase + aoff + mi * (16 * ROWB));
            ldsm4(al[mi], sbase + GTILE + aoff + mi * (16 * ROWB));
        }
        #pragma unroll
        for (int n2 = 0; n2 < 4; n2++) {
            uint32_t bh2[4], bl2[4];
            ldsm4(bh2, sbase + 2 * GTILE + boff + n2 * (16 * ROWB));
            ldsm4(bl2, sbase + 3 * GTILE + boff + n2 * (16 * ROWB));
            #pragma unroll
            for (int mi = 0; mi < 2; mi++) {
                mma_bf16(acc[mi][n2 * 2],     ah[mi], bh2);
                mma_bf16(acc[mi][n2 * 2 + 1], ah[mi], bh2 + 2);
                mma_bf16(acc[mi][n2 * 2],     ah[mi], bl2);
                mma_bf16(acc[mi][n2 * 2 + 1], ah[mi], bl2 + 2);
                mma_bf16(acc[mi][n2 * 2],     al[mi], bh2);
                mma_bf16(acc[mi][n2 * 2 + 1], al[mi], bh2 + 2);
            }
        }
    }

    int g = lane >> 2, t = lane & 3;
    #pragma unroll
    for (int mi = 0; mi < 2; mi++) {
        int row = rowBase + warpM * 32 + mi * 16 + g;
        #pragma unroll
        for (int ni = 0; ni < 8; ni++) {
            int col = colBase + warpN * 64 + ni * 8 + 2 * t;
            *(float2*)(C + (size_t)row * Nc + col)       = make_float2(acc[mi][ni][0], acc[mi][ni][1]);
            *(float2*)(C + (size_t)(row + 8) * Nc + col) = make_float2(acc[mi][ni][2], acc[mi][ni][3]);
        }
    }
}

// ---------------- device-side verification of gemm<0> -------------------------
__global__ void gemm_check_kernel(const float* __restrict__ W) {
    int i = threadIdx.x;
    int row = (i * 67 + 13) & (TOKENS - 1);
    int col = (i * 29 + 3) % NQKV;
    const float* x = g_xn + (size_t)row * DIM;
    float ref = 0.f;
    for (int k = 0; k < DIM; k++) ref = fmaf(x[k], W[(size_t)k * NQKV + col], ref);
    float got = g_qkv[(size_t)row * NQKV + col];
    if (fabsf(got - ref) > 0.02f + 0.01f * fabsf(ref)) g_bad = 1;
}

// ---------------- fp32 fallback GEMM (early-exits unless g_bad) ---------------
template <int MODE>
__global__ __launch_bounds__(256) void sgemm_fb_kernel(const float* __restrict__ B,
                                                       float* __restrict__ Cout) {
    if (g_bad == 0) return;
    constexpr int BM = 128, BN = 128, BK = 16, TM = 8, TN = 8;
    const int N = (MODE == 0) ? NQKV : DIM;
    const float* A = (MODE == 0) ? g_xn : g_ao;
    float* C = (MODE == 0) ? g_qkv : Cout;

    __shared__ __align__(16) float As[BK][BM];
    __shared__ __align__(16) float Bs[BK][BN];

    int tid = threadIdx.x;
    int rowBase = blockIdx.y * BM;
    int colBase = blockIdx.x * BN;
    int lrow = tid >> 1, lk = (tid & 1) * 8;
    int brow = tid >> 4, bc = (tid & 15) * 8;
    int tr = (tid / 16) * TM;
    int tc = (tid % 16) * TN;

    const float* Ap = A + (size_t)(rowBase + lrow) * DIM + lk;
    const float* Bp = B + colBase + (size_t)brow * N + bc;

    float acc[TM * TN];
    #pragma unroll
    for (int i = 0; i < TM * TN; i++) acc[i] = 0.f;

    float4 pa0 = *(const float4*)(Ap + 0);
    float4 pa1 = *(const float4*)(Ap + 4);
    float4 pb0 = *(const float4*)(Bp + 0);
    float4 pb1 = *(const float4*)(Bp + 4);

    const int KT = DIM / BK;
    for (int kt = 0; kt < KT; kt++) {
        As[lk + 0][lrow] = pa0.x; As[lk + 1][lrow] = pa0.y;
        As[lk + 2][lrow] = pa0.z; As[lk + 3][lrow] = pa0.w;
        As[lk + 4][lrow] = pa1.x; As[lk + 5][lrow] = pa1.y;
        As[lk + 6][lrow] = pa1.z; As[lk + 7][lrow] = pa1.w;
        *(float4*)(&Bs[brow][bc])     = pb0;
        *(float4*)(&Bs[brow][bc + 4]) = pb1;
        __syncthreads();
        if (kt + 1 < KT) {
            const float* an = Ap + (kt + 1) * BK;
            const float* bn = Bp + (size_t)(kt + 1) * BK * N;
            pa0 = *(const float4*)(an + 0);
            pa1 = *(const float4*)(an + 4);
            pb0 = *(const float4*)(bn + 0);
            pb1 = *(const float4*)(bn + 4);
        }
        #pragma unroll
        for (int k = 0; k < BK; k++) {
            float rm[TM], rn[TN];
            #pragma unroll
            for (int m = 0; m < TM; m += 4) *(float4*)(rm + m) = *(const float4*)(&As[k][tr + m]);
            #pragma unroll
            for (int n = 0; n < TN; n += 4) *(float4*)(rn + n) = *(const float4*)(&Bs[k][tc + n]);
            #pragma unroll
            for (int m = 0; m < TM; m++)
                #pragma unroll
                for (int n = 0; n < TN; n++)
                    acc[m * TN + n] = fmaf(rm[m], rn[n], acc[m * TN + n]);
        }
        __syncthreads();
    }
    #pragma unroll
    for (int m = 0; m < TM; m++) {
        size_t r = rowBase + tr + m;
        #pragma unroll
        for (int n = 0; n < TN; n += 4)
            *(float4*)(C + r * N + colBase + tc + n) =
                make_float4(acc[m * TN + n], acc[m * TN + n + 1],
                            acc[m * TN + n + 2], acc[m * TN + n + 3]);
    }
}

// ---------------- scatter qkv to (bw,h,s,d) + RoPE; v -> d_out ----------------
__global__ __launch_bounds__(256) void scatter_rope_kernel(float* __restrict__ out_v) {
    int p = blockIdx.x * blockDim.x + threadIdx.x;
    if (p >= TOKENS * (NQKV / 2)) return;
    int t = p / (NQKV / 2);
    int n = (p % (NQKV / 2)) * 2;
    float x0 = g_qkv[(size_t)t * NQKV + n];
    float x1 = g_qkv[(size_t)t * NQKV + n + 1];
    int bw = t / SEG, s = t % SEG;
    int which = n >> 10;
    int nn = n & 1023;
    int h = nn >> 6, d = nn & 63;
    size_t dst = ((size_t)(bw * HEADS + h) * SEG + s) * DH + d;
    if (which == 2) { out_v[dst] = x0; out_v[dst + 1] = x1; return; }
    float c  = g_cos[s * 32 + (d >> 1)];
    float sn = g_sin[s * 32 + (d >> 1)];
    float y0 = x0 * c - x1 * sn;
    float y1 = x1 * c + x0 * sn;
    float* dstp = which ? g_k : g_q;
    dstp[dst] = y0; dstp[dst + 1] = y1;
}

// ---------------- flash attention (fp32) -> fp32 + bf16 hi/lo -----------------
__global__ __launch_bounds__(128) void attn_kernel(const float* __restrict__ vsrc,
                                                   const float* __restrict__ pmem) {
    int bwh = blockIdx.x;
    int h = bwh % HEADS;
    int qt = blockIdx.y;
    int tid = threadIdx.x;

    __shared__ __align__(16) float sm[128 * 64];

    const float* Qb = g_q + ((size_t)bwh * SEG + qt * 128) * DH;
    for (int e = tid; e < 128 * 64; e += 128) sm[e] = Qb[e];
    __syncthreads();
    float q[DH];
    #pragma unroll
    for (int d4 = 0; d4 < DH / 4; d4++) {
        float4 v = *(const float4*)(sm + tid * DH + d4 * 4);
        q[d4 * 4 + 0] = v.x * 0.125f; q[d4 * 4 + 1] = v.y * 0.125f;
        q[d4 * 4 + 2] = v.z * 0.125f; q[d4 * 4 + 3] = v.w * 0.125f;
    }
    __syncthreads();

    float acc[DH];
    #pragma unroll
    for (int d = 0; d < DH; d++) acc[d] = 0.f;
    float m = -1e30f, l = 0.f;
    int i = qt * 128 + tid;
    int nkeys = NPM + i + 1;
    int nch = (NPM + (qt + 1) * 128 + 63) / 64;

    const float* Kb = g_k + (size_t)bwh * SEG * DH;
    const float* Vb = vsrc + (size_t)bwh * SEG * DH;
    const float* PK = pmem + (size_t)h * NPM * DH;
    const float* PV = pmem + (size_t)HEADS * NPM * DH + (size_t)h * NPM * DH;
    float* Ks = sm;
    float* Vs = sm + 64 * 64;

    for (int c = 0; c < nch; c++) {
        for (int e = tid; e < 64 * 64; e += 128) {
            int j = c * 64 + (e >> 6); int d = e & 63;
            float kv, vv;
            if (j < NPM)            { kv = PK[j * DH + d];                 vv = PV[j * DH + d]; }
            else if (j < NPM + SEG) { kv = Kb[(size_t)(j - NPM) * DH + d]; vv = Vb[(size_t)(j - NPM) * DH + d]; }
            else                    { kv = 0.f; vv = 0.f; }
            Ks[e] = kv; Vs[e] = vv;
        }
        __syncthreads();
        int jvalid = nkeys - c * 64;
        #pragma unroll 2
        for (int j = 0; j < 64; j++) {
            float s = 0.f;
            const float4* kp = (const float4*)(Ks + j * 64);
            #pragma unroll
            for (int d4 = 0; d4 < DH / 4; d4++) {
                float4 kk = kp[d4];
                s = fmaf(q[d4 * 4 + 0], kk.x, s);
                s = fmaf(q[d4 * 4 + 1], kk.y, s);
                s = fmaf(q[d4 * 4 + 2], kk.z, s);
                s = fmaf(q[d4 * 4 + 3], kk.w, s);
            }
            if (j >= jvalid) s = -1e30f;
            if (s > m) {
                float corr = __expf(m - s);
                l *= corr;
                #pragma unroll
                for (int d = 0; d < DH; d++) acc[d] *= corr;
                m = s;
            }
            float p = __expf(s - m);
            l += p;
            const float4* vp = (const float4*)(Vs + j * 64);
            #pragma unroll
            for (int d4 = 0; d4 < DH / 4; d4++) {
                float4 vv = vp[d4];
                acc[d4 * 4 + 0] = fmaf(p, vv.x, acc[d4 * 4 + 0]);
                acc[d4 * 4 + 1] = fmaf(p, vv.y, acc[d4 * 4 + 1]);
                acc[d4 * 4 + 2] = fmaf(p, vv.z, acc[d4 * 4 + 2]);
                acc[d4 * 4 + 3] = fmaf(p, vv.w, acc[d4 * 4 + 3]);
            }
        }
        __syncthreads();
    }
    int bw = bwh / HEADS;
    float rl = 1.0f / l;
    size_t obase = ((size_t)(bw * SEG + i)) * DIM + (size_t)h * DH;
    #pragma unroll
    for (int d = 0; d < DH; d += 2) {
        float v0 = acc[d] * rl, v1 = acc[d + 1] * rl;
        g_ao[obase + d] = v0; g_ao[obase + d + 1] = v1;
        __nv_bfloat16 h0 = __float2bfloat16(v0), h1 = __float2bfloat16(v1);
        __nv_bfloat16 l0 = __float2bfloat16(v0 - __bfloat162float(h0));
        __nv_bfloat16 l1 = __float2bfloat16(v1 - __bfloat162float(h1));
        *(__nv_bfloat162*)(g_o_hi + obase + d) = __halves2bfloat162(h0, h1);
        *(__nv_bfloat162*)(g_o_lo + obase + d) = __halves2bfloat162(l0, l1);
    }
}

// --------- launch (ONLY harness pointers cross the host boundary) -------------
extern "C" void kernel_launch(void* const* d_in, const int* in_sizes, int n_in,
                              void* d_out, int out_size) {
    const float* seq    = (const float*)d_in[0];
    const float* norm_w = (const float*)d_in[1];
    const float* w_qkv  = (const float*)d_in[2];
    const float* w_out  = (const float*)d_in[3];
    const float* pmem   = (const float*)d_in[4];
    float* out   = (float*)d_out;
    float* out_v = out + (size_t)TOKENS * DIM;

    rope_table_kernel<<<64, 256>>>();
    wconv_kernel<0><<<(NQKV * DIM + 255) / 256, 256>>>(w_qkv);
    wconv_kernel<1><<<(DIM * DIM + 255) / 256, 256>>>(w_out);
    rmsnorm_kernel<<<TOKENS, 256>>>(seq, norm_w);
    gemm_kernel<0><<<dim3(NQKV / 128, TOKENS / 128), 256>>>(nullptr);
    gemm_check_kernel<<<1, 128>>>(w_qkv);
    sgemm_fb_kernel<0><<<dim3(NQKV / 128, TOKENS / 128), 256>>>(w_qkv, nullptr);
    scatter_rope_kernel<<<(TOKENS * (NQKV / 2) + 255) / 256, 256>>>(out_v);
    attn_kernel<<<dim3(256, 4), 128>>>(out_v, pmem);
    gemm_kernel<1><<<dim3(DIM / 128, TOKENS / 128), 256>>>(out);
    sgemm_fb_kernel<1><<<dim3(DIM / 128, TOKENS / 128), 256>>>(w_out, out);
}